// round 6
// baseline (speedup 1.0000x reference)
#include <cuda_runtime.h>
#include <cuda_bf16.h>

#define BB 64
#define TT 512
#define DD 768
#define LL 50

typedef unsigned long long ull;

// ---------- f32x2 helpers (sm_103a packed fp32) ----------
__device__ __forceinline__ ull pack2(float x, float y) {
    ull r;
    asm("mov.b64 %0, {%1,%2};" : "=l"(r) : "f"(x), "f"(y));
    return r;
}
__device__ __forceinline__ void unpack2(ull v, float& x, float& y) {
    asm("mov.b64 {%0,%1}, %2;" : "=f"(x), "=f"(y) : "l"(v));
}
__device__ __forceinline__ void fma2(ull& d, ull a, ull b) {
    asm("fma.rn.f32x2 %0, %1, %2, %0;" : "+l"(d) : "l"(a), "l"(b));
}
__device__ __forceinline__ ull add2(ull a, ull b) {
    ull r;
    asm("add.rn.f32x2 %0, %1, %2;" : "=l"(r) : "l"(a), "l"(b));
    return r;
}
__device__ __forceinline__ float frcp_fast(float x) {
    float r;
    asm("rcp.approx.f32 %0, %1;" : "=f"(r) : "f"(x));
    return r;
}
__device__ __forceinline__ float wred_addf(float x) {
#pragma unroll
    for (int o = 16; o > 0; o >>= 1) x += __shfl_xor_sync(0xffffffffu, x, o);
    return x;
}
__device__ __forceinline__ int wred_addi(int x) {
#pragma unroll
    for (int o = 16; o > 0; o >>= 1) x += __shfl_xor_sync(0xffffffffu, x, o);
    return x;
}

// ---------- GEMM: logits = emb @ W + b ----------
#define AP 129
__global__ void __launch_bounds__(128, 3)
gemm_kernel(const float* __restrict__ A, const float* __restrict__ W,
            const float* __restrict__ bias, float* __restrict__ logits,
            float* __restrict__ loss0) {
    __shared__ float Ash[64 * AP];
    __shared__ __align__(16) float Wsh[64 * 52];
    __shared__ float bsh[52];

    int tid = threadIdx.x;
    if (blockIdx.x == 0 && tid == 0) *loss0 = 0.0f;
    if (tid < 52) bsh[tid] = (tid < LL) ? bias[tid] : 0.0f;

    ull acc[26];
#pragma unroll
    for (int p = 0; p < 26; p++) acc[p] = 0ull;

    const float4* Ag = reinterpret_cast<const float4*>(A);
    int rowbase = blockIdx.x * 128;

    for (int kt = 0; kt < DD / 64; kt++) {
        __syncthreads();
#pragma unroll
        for (int it = 0; it < 16; it++) {
            int idx = it * 128 + tid;
            int q = idx & 15;
            int r = idx >> 4;
            float4 f = Ag[(size_t)(rowbase + r) * (DD / 4) + kt * 16 + q];
            Ash[(4 * q + 0) * AP + r] = f.x;
            Ash[(4 * q + 1) * AP + r] = f.y;
            Ash[(4 * q + 2) * AP + r] = f.z;
            Ash[(4 * q + 3) * AP + r] = f.w;
        }
        for (int idx = tid; idx < 64 * 52; idx += 128) {
            int kk = idx / 52;
            int j = idx - kk * 52;
            Wsh[idx] = (j < LL) ? W[(size_t)(kt * 64 + kk) * LL + j] : 0.0f;
        }
        __syncthreads();
#pragma unroll 8
        for (int kk = 0; kk < 64; kk++) {
            float a = Ash[kk * AP + tid];
            ull ap = pack2(a, a);
            const ulonglong2* w2 = reinterpret_cast<const ulonglong2*>(Wsh + kk * 52);
#pragma unroll
            for (int p = 0; p < 13; p++) {
                ulonglong2 w = w2[p];
                fma2(acc[2 * p + 0], ap, w.x);
                fma2(acc[2 * p + 1], ap, w.y);
            }
        }
    }
    __syncthreads();
    float* st = Ash;
#pragma unroll
    for (int p = 0; p < 25; p++) {
        float x, y;
        unpack2(acc[p], x, y);
        st[tid * 50 + 2 * p + 0] = x + bsh[2 * p + 0];
        st[tid * 50 + 2 * p + 1] = y + bsh[2 * p + 1];
    }
    __syncthreads();
    size_t base = (size_t)blockIdx.x * (128 * LL);
    for (int idx = tid; idx < 128 * LL; idx += 128)
        logits[base + idx] = st[idx];
}

// ---------- mask decode ----------
__device__ __forceinline__ bool mask_on(const void* m, int mode, int idx) {
    if (mode == 0) return ((const int*)m)[idx] != 0;
    if (mode == 1) return ((const unsigned char*)m)[idx] != 0;
    return ((const float*)m)[idx] != 0.0f;
}

// ---------- CRF: 2 batches per block, 64 threads ----------
// Warp 0: forward recurrences for BOTH batches interleaved (latency hiding).
//   Layout per batch: lane u (u<25) owns states j0=2u, j1=2u+1; E in regs.
// Warp 1: gold-path numerators for both batches.
__global__ void __launch_bounds__(64, 1)
crf_kernel(const float* __restrict__ logits, const int* __restrict__ labels,
           const void* __restrict__ maskraw, const float* __restrict__ startT,
           const float* __restrict__ endT, const float* __restrict__ trans,
           float* __restrict__ loss0) {
    __shared__ __align__(16) ull pd0[2][32], pd1[2][32];  // p-vector pairs per batch
    __shared__ float res_den0, res_den1, res_num0, res_num1;

    int tid = threadIdx.x;
    int wid = tid >> 5;
    int u = tid & 31;
    int b0 = 2 * blockIdx.x, b1 = b0 + 1;

    const float* l0 = logits + (size_t)b0 * TT * LL;
    const float* l1 = logits + (size_t)b1 * TT * LL;

    // mask encoding + lengths (contiguous prefixes), computed by each warp
    int mw = *(const int*)maskraw;
    int mode = (mw == 1) ? 0 : ((mw == 0x01010101) ? 1 : 2);
    int c0 = 0, c1 = 0;
    for (int t = u; t < TT; t += 32) {
        c0 += mask_on(maskraw, mode, b0 * TT + t) ? 1 : 0;
        c1 += mask_on(maskraw, mode, b1 * TT + t) ? 1 : 0;
    }
    int len0 = wred_addi(c0);
    int len1 = wred_addi(c1);
    int lenmax = len0 > len1 ? len0 : len1;

    if (wid == 0) {
        int j0 = 2 * u, j1 = 2 * u + 1;
        bool act = (u < 25);
        int jc = act ? j0 : 0;

        // E in registers (shared by both batches):
        // E0[i]=(e[2i][j0], e[2i+1][j0]), E1[i] same for j1
        ull E0[25], E1[25];
#pragma unroll
        for (int i = 0; i < 25; i++) {
            float a0 = 0.0f, a1 = 0.0f, d0 = 0.0f, d1 = 0.0f;
            if (act) {
                a0 = __expf(trans[(2 * i) * LL + j0]);
                a1 = __expf(trans[(2 * i + 1) * LL + j0]);
                d0 = __expf(trans[(2 * i) * LL + j1]);
                d1 = __expf(trans[(2 * i + 1) * LL + j1]);
            }
            E0[i] = pack2(a0, a1);
            E1[i] = pack2(d0, d1);
        }

        float v0x = 0.0f, v0y = 0.0f, v1x = 0.0f, v1y = 0.0f;
        if (act) {
            v0x = __expf(startT[j0] + l0[j0]);
            v0y = __expf(startT[j1] + l0[j1]);
            v1x = __expf(startT[j0] + l1[j0]);
            v1y = __expf(startT[j1] + l1[j1]);
        }
        float S0 = 0.0f, S1 = 0.0f;

        // depth-4 emission prefetch rings (scalar loads; logits is 4B-aligned)
        float g0x[4], g0y[4], g1x[4], g1y[4];
#pragma unroll
        for (int k = 0; k < 4; k++) {
            size_t o = (size_t)(1 + k) * LL + jc;
            g0x[k] = l0[o];
            g0y[k] = l0[o + 1];
            g1x[k] = l1[o];
            g1y[k] = l1[o + 1];
        }

#pragma unroll 4
        for (int t = 1; t < lenmax; t++) {
            int slot = (t - 1) & 3;
            int buf = t & 1;
            bool u0 = (t < len0), u1 = (t < len1);
            if (u0) pd0[buf][u] = pack2(v0x, v0y);
            if (u1) pd1[buf][u] = pack2(v1x, v1y);
            __syncwarp();
            int tp = t + 4;
            if (tp > TT - 1) tp = TT - 1;
            size_t off = (size_t)tp * LL + jc;

            if (u0) {
                const ulonglong2* pp2 = reinterpret_cast<const ulonglong2*>(pd0[buf]);
                ull A00 = 0ull, A01 = 0ull, A10 = 0ull, A11 = 0ull;
                ulonglong2 Pq0 = pp2[0];
                float v0b, dmy;
                unpack2(Pq0.x, v0b, dmy);
                fma2(A00, Pq0.x, E0[0]);
                fma2(A10, Pq0.x, E1[0]);
                fma2(A01, Pq0.y, E0[1]);
                fma2(A11, Pq0.y, E1[1]);
#pragma unroll
                for (int q = 1; q < 12; q++) {
                    ulonglong2 Pq = pp2[q];
                    fma2(A00, Pq.x, E0[2 * q]);
                    fma2(A10, Pq.x, E1[2 * q]);
                    fma2(A01, Pq.y, E0[2 * q + 1]);
                    fma2(A11, Pq.y, E1[2 * q + 1]);
                }
                ull P24 = pd0[buf][24];
                fma2(A00, P24, E0[24]);
                fma2(A10, P24, E1[24]);
                float r = frcp_fast(v0b);
                S0 += __logf(v0b);
                float wx = __expf(g0x[slot]);
                float wy = __expf(g0y[slot]);
                ull sj0 = add2(A00, A01);
                ull sj1 = add2(A10, A11);
                float e0, e1, f0, f1;
                unpack2(sj0, e0, e1);
                unpack2(sj1, f0, f1);
                v0x = (e0 + e1) * wx * r;
                v0y = (f0 + f1) * wy * r;
                g0x[slot] = l0[off];
                g0y[slot] = l0[off + 1];
            }
            if (u1) {
                const ulonglong2* pp2 = reinterpret_cast<const ulonglong2*>(pd1[buf]);
                ull A00 = 0ull, A01 = 0ull, A10 = 0ull, A11 = 0ull;
                ulonglong2 Pq0 = pp2[0];
                float v0b, dmy;
                unpack2(Pq0.x, v0b, dmy);
                fma2(A00, Pq0.x, E0[0]);
                fma2(A10, Pq0.x, E1[0]);
                fma2(A01, Pq0.y, E0[1]);
                fma2(A11, Pq0.y, E1[1]);
#pragma unroll
                for (int q = 1; q < 12; q++) {
                    ulonglong2 Pq = pp2[q];
                    fma2(A00, Pq.x, E0[2 * q]);
                    fma2(A10, Pq.x, E1[2 * q]);
                    fma2(A01, Pq.y, E0[2 * q + 1]);
                    fma2(A11, Pq.y, E1[2 * q + 1]);
                }
                ull P24 = pd1[buf][24];
                fma2(A00, P24, E0[24]);
                fma2(A10, P24, E1[24]);
                float r = frcp_fast(v0b);
                S1 += __logf(v0b);
                float wx = __expf(g1x[slot]);
                float wy = __expf(g1y[slot]);
                ull sj0 = add2(A00, A01);
                ull sj1 = add2(A10, A11);
                float e0, e1, f0, f1;
                unpack2(sj0, e0, e1);
                unpack2(sj1, f0, f1);
                v1x = (e0 + e1) * wx * r;
                v1y = (f0 + f1) * wy * r;
                g1x[slot] = l1[off];
                g1y[slot] = l1[off + 1];
            }
        }

        // denominators
        float ee0 = act ? __expf(endT[j0]) : 0.0f;
        float ee1 = act ? __expf(endT[j1]) : 0.0f;
        float s0 = wred_addf(v0x * ee0 + v0y * ee1);
        float s1 = wred_addf(v1x * ee0 + v1y * ee1);
        if (u == 0) {
            res_den0 = __logf(s0) + S0;
            res_den1 = __logf(s1) + S1;
        }
    } else {
        // ---- numerators (prefix mask => prev tag = labels[t-1]) ----
        const int* la0 = labels + b0 * TT;
        const int* la1 = labels + b1 * TT;
        float n0 = 0.0f, n1 = 0.0f;
        for (int t = u; t < lenmax; t += 32) {
            if (t < len0) {
                int tag = la0[t];
                float emv = l0[(size_t)t * LL + tag];
                n0 += (t == 0) ? (startT[tag] + emv)
                               : (trans[la0[t - 1] * LL + tag] + emv);
                if (t == len0 - 1) n0 += endT[tag];
            }
            if (t < len1) {
                int tag = la1[t];
                float emv = l1[(size_t)t * LL + tag];
                n1 += (t == 0) ? (startT[tag] + emv)
                               : (trans[la1[t - 1] * LL + tag] + emv);
                if (t == len1 - 1) n1 += endT[tag];
            }
        }
        float num0 = wred_addf(n0);
        float num1 = wred_addf(n1);
        if (u == 0) {
            res_num0 = num0;
            res_num1 = num1;
        }
    }
    __syncthreads();
    if (tid == 0)
        atomicAdd(loss0, ((res_den0 - res_num0) + (res_den1 - res_num1)) *
                             (1.0f / (float)BB));
}

extern "C" void kernel_launch(void* const* d_in, const int* in_sizes, int n_in,
                              void* d_out, int out_size) {
    (void)in_sizes; (void)n_in; (void)out_size;
    const float* emb    = (const float*)d_in[0];
    const int*   labels = (const int*)d_in[1];
    const void*  mask   = d_in[2];
    const float* W      = (const float*)d_in[3];
    const float* bias   = (const float*)d_in[4];
    const float* startT = (const float*)d_in[5];
    const float* endT   = (const float*)d_in[6];
    const float* trans  = (const float*)d_in[7];

    float* out = (float*)d_out;
    float* logits = out + 1;  // output layout: [ -loss, logits(B*T*L) ]

    gemm_kernel<<<256, 128>>>(emb, W, bias, logits, out);
    crf_kernel<<<BB / 2, 64>>>(logits, labels, mask, startT, endT, trans, out);
}

// round 7
// speedup vs baseline: 1.3274x; 1.3274x over previous
#include <cuda_runtime.h>
#include <cuda_bf16.h>

#define BB 64
#define TT 512
#define DD 768
#define LL 50

typedef unsigned long long ull;

// ---------- f32x2 helpers (sm_103a packed fp32) ----------
__device__ __forceinline__ ull pack2(float x, float y) {
    ull r;
    asm("mov.b64 %0, {%1,%2};" : "=l"(r) : "f"(x), "f"(y));
    return r;
}
__device__ __forceinline__ void unpack2(ull v, float& x, float& y) {
    asm("mov.b64 {%0,%1}, %2;" : "=f"(x), "=f"(y) : "l"(v));
}
__device__ __forceinline__ void fma2(ull& d, ull a, ull b) {
    asm("fma.rn.f32x2 %0, %1, %2, %0;" : "+l"(d) : "l"(a), "l"(b));
}
__device__ __forceinline__ ull add2(ull a, ull b) {
    ull r;
    asm("add.rn.f32x2 %0, %1, %2;" : "=l"(r) : "l"(a), "l"(b));
    return r;
}
__device__ __forceinline__ float frcp_fast(float x) {
    float r;
    asm("rcp.approx.f32 %0, %1;" : "=f"(r) : "f"(x));
    return r;
}
__device__ __forceinline__ float wred_addf(float x) {
#pragma unroll
    for (int o = 16; o > 0; o >>= 1) x += __shfl_xor_sync(0xffffffffu, x, o);
    return x;
}
__device__ __forceinline__ int wred_addi(int x) {
#pragma unroll
    for (int o = 16; o > 0; o >>= 1) x += __shfl_xor_sync(0xffffffffu, x, o);
    return x;
}

// ---------- GEMM: logits = emb @ W + b ----------
#define AP 129
__global__ void __launch_bounds__(128, 3)
gemm_kernel(const float* __restrict__ A, const float* __restrict__ W,
            const float* __restrict__ bias, float* __restrict__ logits,
            float* __restrict__ loss0) {
    __shared__ float Ash[64 * AP];
    __shared__ __align__(16) float Wsh[64 * 52];
    __shared__ float bsh[52];

    int tid = threadIdx.x;
    if (blockIdx.x == 0 && tid == 0) *loss0 = 0.0f;
    if (tid < 52) bsh[tid] = (tid < LL) ? bias[tid] : 0.0f;

    ull acc[26];
#pragma unroll
    for (int p = 0; p < 26; p++) acc[p] = 0ull;

    const float4* Ag = reinterpret_cast<const float4*>(A);
    int rowbase = blockIdx.x * 128;

    for (int kt = 0; kt < DD / 64; kt++) {
        __syncthreads();
#pragma unroll
        for (int it = 0; it < 16; it++) {
            int idx = it * 128 + tid;
            int q = idx & 15;
            int r = idx >> 4;
            float4 f = Ag[(size_t)(rowbase + r) * (DD / 4) + kt * 16 + q];
            Ash[(4 * q + 0) * AP + r] = f.x;
            Ash[(4 * q + 1) * AP + r] = f.y;
            Ash[(4 * q + 2) * AP + r] = f.z;
            Ash[(4 * q + 3) * AP + r] = f.w;
        }
        for (int idx = tid; idx < 64 * 52; idx += 128) {
            int kk = idx / 52;
            int j = idx - kk * 52;
            Wsh[idx] = (j < LL) ? W[(size_t)(kt * 64 + kk) * LL + j] : 0.0f;
        }
        __syncthreads();
#pragma unroll 8
        for (int kk = 0; kk < 64; kk++) {
            float a = Ash[kk * AP + tid];
            ull ap = pack2(a, a);
            const ulonglong2* w2 = reinterpret_cast<const ulonglong2*>(Wsh + kk * 52);
#pragma unroll
            for (int p = 0; p < 13; p++) {
                ulonglong2 w = w2[p];
                fma2(acc[2 * p + 0], ap, w.x);
                fma2(acc[2 * p + 1], ap, w.y);
            }
        }
    }
    __syncthreads();
    float* st = Ash;
#pragma unroll
    for (int p = 0; p < 25; p++) {
        float x, y;
        unpack2(acc[p], x, y);
        st[tid * 50 + 2 * p + 0] = x + bsh[2 * p + 0];
        st[tid * 50 + 2 * p + 1] = y + bsh[2 * p + 1];
    }
    __syncthreads();
    size_t base = (size_t)blockIdx.x * (128 * LL);
    for (int idx = tid; idx < 128 * LL; idx += 128)
        logits[base + idx] = st[idx];
}

// ---------- mask decode ----------
__device__ __forceinline__ bool mask_on(const void* m, int mode, int idx) {
    if (mode == 0) return ((const int*)m)[idx] != 0;
    if (mode == 1) return ((const unsigned char*)m)[idx] != 0;
    return ((const float*)m)[idx] != 0.0f;
}

// ---------- CRF: one block per batch, forward+backward split ----------
// smem: exp(logits) tile (100KB). Warp 0: alpha forward [0..m].
// Warp 1: beta backward [len-1..m]. Warp 2: gold-path numerator.
// den = log(dot(vf,vb)) + Sf + Sb.
__global__ void __launch_bounds__(128, 1)
crf_kernel(const float* __restrict__ logits, const int* __restrict__ labels,
           const void* __restrict__ maskraw, const float* __restrict__ startT,
           const float* __restrict__ endT, const float* __restrict__ trans,
           float* __restrict__ loss0) {
    extern __shared__ float em[];                       // [TT*LL] exp(logits)
    __shared__ __align__(16) ull pdf[2][32], pdb[2][32];
    __shared__ float vf[64], vb[64];
    __shared__ float Ssh[2];
    __shared__ float res_den, res_num;

    int b = blockIdx.x;
    int tid = threadIdx.x;
    int wid = tid >> 5;
    int u = tid & 31;

    const float* lrow0 = logits + (size_t)b * TT * LL;

    // mask encoding + length (contiguous prefix)
    int mw = *(const int*)maskraw;
    int mode = (mw == 1) ? 0 : ((mw == 0x01010101) ? 1 : 2);
    int cnt = 0;
    for (int t = u; t < TT; t += 32) cnt += mask_on(maskraw, mode, b * TT + t) ? 1 : 0;
    int len = wred_addi(cnt);
    int m = len >> 1;

    // preload exp(logits) (all 128 threads)
    for (int idx = tid; idx < TT * LL; idx += 128) em[idx] = __expf(lrow0[idx]);
    if (tid < 64) { vf[tid] = 0.0f; vb[tid] = 0.0f; }
    __syncthreads();

    int j0 = 2 * u, j1 = 2 * u + 1;
    bool act = (u < 25);
    int jc = act ? j0 : 0;

    if (wid == 0) {
        // ---- forward: alpha over [0..m] ----
        // E columns: EF0[i]=(e[2i][j0],e[2i+1][j0]); EF1 for j1
        ull EF0[25], EF1[25];
#pragma unroll
        for (int i = 0; i < 25; i++) {
            float a0 = 0.0f, a1 = 0.0f, d0 = 0.0f, d1 = 0.0f;
            if (act) {
                a0 = __expf(trans[(2 * i) * LL + j0]);
                a1 = __expf(trans[(2 * i + 1) * LL + j0]);
                d0 = __expf(trans[(2 * i) * LL + j1]);
                d1 = __expf(trans[(2 * i + 1) * LL + j1]);
            }
            EF0[i] = pack2(a0, a1);
            EF1[i] = pack2(d0, d1);
        }

        float vx = 0.0f, vy = 0.0f;
        if (act) {
            vx = __expf(startT[j0] + lrow0[j0]);
            vy = __expf(startT[j1] + lrow0[j1]);
        }
        float S = 0.0f;

        for (int t = 1; t <= m; t++) {
            int buf = t & 1;
            pdf[buf][u] = pack2(vx, vy);
            __syncwarp();
            float wx = em[t * LL + jc];
            float wy = em[t * LL + jc + 1];
            const ulonglong2* pp2 = reinterpret_cast<const ulonglong2*>(pdf[buf]);
            ull A00 = 0ull, A01 = 0ull, A10 = 0ull, A11 = 0ull;
            ulonglong2 Pq0 = pp2[0];
            float v0b, dmy;
            unpack2(Pq0.x, v0b, dmy);
            fma2(A00, Pq0.x, EF0[0]);
            fma2(A10, Pq0.x, EF1[0]);
            fma2(A01, Pq0.y, EF0[1]);
            fma2(A11, Pq0.y, EF1[1]);
#pragma unroll
            for (int q = 1; q < 12; q++) {
                ulonglong2 Pq = pp2[q];
                fma2(A00, Pq.x, EF0[2 * q]);
                fma2(A10, Pq.x, EF1[2 * q]);
                fma2(A01, Pq.y, EF0[2 * q + 1]);
                fma2(A11, Pq.y, EF1[2 * q + 1]);
            }
            ull P24 = pdf[buf][24];
            fma2(A00, P24, EF0[24]);
            fma2(A10, P24, EF1[24]);
            float r = frcp_fast(v0b);
            S += __logf(v0b);
            ull sj0 = add2(A00, A01);
            ull sj1 = add2(A10, A11);
            float e0, e1, f0, f1;
            unpack2(sj0, e0, e1);
            unpack2(sj1, f0, f1);
            vx = (e0 + e1) * wx * r;
            vy = (f0 + f1) * wy * r;
        }

        if (act) { vf[j0] = vx; vf[j1] = vy; }
        if (u == 0) Ssh[0] = S;
    } else if (wid == 1) {
        // ---- backward: beta over [len-1..m] ----
        // E rows: EB0[k]=(e[i0][2k],e[i0][2k+1]); EB1 for i1  (i0=j0,i1=j1)
        ull EB0[25], EB1[25];
#pragma unroll
        for (int k = 0; k < 25; k++) {
            float a0 = 0.0f, a1 = 0.0f, d0 = 0.0f, d1 = 0.0f;
            if (act) {
                a0 = __expf(trans[j0 * LL + 2 * k]);
                a1 = __expf(trans[j0 * LL + 2 * k + 1]);
                d0 = __expf(trans[j1 * LL + 2 * k]);
                d1 = __expf(trans[j1 * LL + 2 * k + 1]);
            }
            EB0[k] = pack2(a0, a1);
            EB1[k] = pack2(d0, d1);
        }

        float ux = 0.0f, uy = 0.0f;
        if (act) {
            ux = __expf(endT[j0]);
            uy = __expf(endT[j1]);
        }
        float S = 0.0f;

        for (int cur = len - 2; cur >= m; cur--) {
            int buf = cur & 1;
            // q = w_{cur+1} ∘ u
            float wx = em[(cur + 1) * LL + jc];
            float wy = em[(cur + 1) * LL + jc + 1];
            pdb[buf][u] = pack2(ux * wx, uy * wy);
            __syncwarp();
            const ulonglong2* pp2 = reinterpret_cast<const ulonglong2*>(pdb[buf]);
            ull A00 = 0ull, A01 = 0ull, A10 = 0ull, A11 = 0ull;
            ulonglong2 Pq0 = pp2[0];
            float q0b, dmy;
            unpack2(Pq0.x, q0b, dmy);
            fma2(A00, Pq0.x, EB0[0]);
            fma2(A10, Pq0.x, EB1[0]);
            fma2(A01, Pq0.y, EB0[1]);
            fma2(A11, Pq0.y, EB1[1]);
#pragma unroll
            for (int q = 1; q < 12; q++) {
                ulonglong2 Pq = pp2[q];
                fma2(A00, Pq.x, EB0[2 * q]);
                fma2(A10, Pq.x, EB1[2 * q]);
                fma2(A01, Pq.y, EB0[2 * q + 1]);
                fma2(A11, Pq.y, EB1[2 * q + 1]);
            }
            ull P24 = pdb[buf][24];
            fma2(A00, P24, EB0[24]);
            fma2(A10, P24, EB1[24]);
            float r = frcp_fast(q0b);
            S += __logf(q0b);
            ull sj0 = add2(A00, A01);
            ull sj1 = add2(A10, A11);
            float e0, e1, f0, f1;
            unpack2(sj0, e0, e1);
            unpack2(sj1, f0, f1);
            ux = (e0 + e1) * r;
            uy = (f0 + f1) * r;
        }

        if (act) { vb[j0] = ux; vb[j1] = uy; }
        if (u == 0) Ssh[1] = S;
    } else if (wid == 2) {
        // ---- numerator (prefix mask => prev tag = labels[t-1]) ----
        float np = 0.0f;
        const int* lab = labels + b * TT;
        for (int t = u; t < len; t += 32) {
            int tag = lab[t];
            float emv = lrow0[(size_t)t * LL + tag];
            np += (t == 0) ? (startT[tag] + emv)
                           : (trans[lab[t - 1] * LL + tag] + emv);
            if (t == len - 1) np += endT[tag];
        }
        float num = wred_addf(np);
        if (u == 0) res_num = num;
    }
    __syncthreads();

    // combine: den = log(dot(vf,vb)) + Sf + Sb
    if (wid == 0) {
        float s = act ? (vf[j0] * vb[j0] + vf[j1] * vb[j1]) : 0.0f;
        s = wred_addf(s);
        if (u == 0) res_den = __logf(s) + Ssh[0] + Ssh[1];
    }
    __syncthreads();
    if (tid == 0) atomicAdd(loss0, (res_den - res_num) * (1.0f / (float)BB));
}

extern "C" void kernel_launch(void* const* d_in, const int* in_sizes, int n_in,
                              void* d_out, int out_size) {
    (void)in_sizes; (void)n_in; (void)out_size;
    const float* emb    = (const float*)d_in[0];
    const int*   labels = (const int*)d_in[1];
    const void*  mask   = d_in[2];
    const float* W      = (const float*)d_in[3];
    const float* bias   = (const float*)d_in[4];
    const float* startT = (const float*)d_in[5];
    const float* endT   = (const float*)d_in[6];
    const float* trans  = (const float*)d_in[7];

    float* out = (float*)d_out;
    float* logits = out + 1;  // output layout: [ -loss, logits(B*T*L) ]

    const int dyn = TT * LL * sizeof(float);  // 102,400 B
    cudaFuncSetAttribute(crf_kernel, cudaFuncAttributeMaxDynamicSharedMemorySize, dyn);

    gemm_kernel<<<256, 128>>>(emb, W, bias, logits, out);
    crf_kernel<<<BB, 128, dyn>>>(logits, labels, mask, startT, endT, trans, out);
}

// round 8
// speedup vs baseline: 2.1222x; 1.5987x over previous
#include <cuda_runtime.h>
#include <cuda_bf16.h>

#define BB 64
#define TT 512
#define DD 768
#define LL 50

typedef unsigned long long ull;

// ---------- f32x2 helpers (sm_103a packed fp32) ----------
__device__ __forceinline__ ull pack2(float x, float y) {
    ull r;
    asm("mov.b64 %0, {%1,%2};" : "=l"(r) : "f"(x), "f"(y));
    return r;
}
__device__ __forceinline__ void unpack2(ull v, float& x, float& y) {
    asm("mov.b64 {%0,%1}, %2;" : "=f"(x), "=f"(y) : "l"(v));
}
__device__ __forceinline__ void fma2(ull& d, ull a, ull b) {
    asm("fma.rn.f32x2 %0, %1, %2, %0;" : "+l"(d) : "l"(a), "l"(b));
}
__device__ __forceinline__ ull add2(ull a, ull b) {
    ull r;
    asm("add.rn.f32x2 %0, %1, %2;" : "=l"(r) : "l"(a), "l"(b));
    return r;
}
__device__ __forceinline__ float frcp_fast(float x) {
    float r;
    asm("rcp.approx.f32 %0, %1;" : "=f"(r) : "f"(x));
    return r;
}
__device__ __forceinline__ float wred_addf(float x) {
#pragma unroll
    for (int o = 16; o > 0; o >>= 1) x += __shfl_xor_sync(0xffffffffu, x, o);
    return x;
}
__device__ __forceinline__ int wred_addi(int x) {
#pragma unroll
    for (int o = 16; o > 0; o >>= 1) x += __shfl_xor_sync(0xffffffffu, x, o);
    return x;
}

// ---------- GEMM: logits = emb @ W + b ----------
#define AP 129
__global__ void __launch_bounds__(128, 3)
gemm_kernel(const float* __restrict__ A, const float* __restrict__ W,
            const float* __restrict__ bias, float* __restrict__ logits,
            float* __restrict__ loss0) {
    __shared__ float Ash[64 * AP];
    __shared__ __align__(16) float Wsh[64 * 52];
    __shared__ float bsh[52];

    int tid = threadIdx.x;
    if (blockIdx.x == 0 && tid == 0) *loss0 = 0.0f;
    if (tid < 52) bsh[tid] = (tid < LL) ? bias[tid] : 0.0f;

    ull acc[26];
#pragma unroll
    for (int p = 0; p < 26; p++) acc[p] = 0ull;

    const float4* Ag = reinterpret_cast<const float4*>(A);
    int rowbase = blockIdx.x * 128;

    for (int kt = 0; kt < DD / 64; kt++) {
        __syncthreads();
#pragma unroll
        for (int it = 0; it < 16; it++) {
            int idx = it * 128 + tid;
            int q = idx & 15;
            int r = idx >> 4;
            float4 f = Ag[(size_t)(rowbase + r) * (DD / 4) + kt * 16 + q];
            Ash[(4 * q + 0) * AP + r] = f.x;
            Ash[(4 * q + 1) * AP + r] = f.y;
            Ash[(4 * q + 2) * AP + r] = f.z;
            Ash[(4 * q + 3) * AP + r] = f.w;
        }
        for (int idx = tid; idx < 64 * 52; idx += 128) {
            int kk = idx / 52;
            int j = idx - kk * 52;
            Wsh[idx] = (j < LL) ? W[(size_t)(kt * 64 + kk) * LL + j] : 0.0f;
        }
        __syncthreads();
#pragma unroll 8
        for (int kk = 0; kk < 64; kk++) {
            float a = Ash[kk * AP + tid];
            ull ap = pack2(a, a);
            const ulonglong2* w2 = reinterpret_cast<const ulonglong2*>(Wsh + kk * 52);
#pragma unroll
            for (int p = 0; p < 13; p++) {
                ulonglong2 w = w2[p];
                fma2(acc[2 * p + 0], ap, w.x);
                fma2(acc[2 * p + 1], ap, w.y);
            }
        }
    }
    __syncthreads();
    float* st = Ash;
#pragma unroll
    for (int p = 0; p < 25; p++) {
        float x, y;
        unpack2(acc[p], x, y);
        st[tid * 50 + 2 * p + 0] = x + bsh[2 * p + 0];
        st[tid * 50 + 2 * p + 1] = y + bsh[2 * p + 1];
    }
    __syncthreads();
    size_t base = (size_t)blockIdx.x * (128 * LL);
    for (int idx = tid; idx < 128 * LL; idx += 128)
        logits[base + idx] = st[idx];
}

// ---------- mask decode ----------
__device__ __forceinline__ bool mask_on(const void* m, int mode, int idx) {
    if (mode == 0) return ((const int*)m)[idx] != 0;
    if (mode == 1) return ((const unsigned char*)m)[idx] != 0;
    return ((const float*)m)[idx] != 0.0f;
}

// ---------- CRF: one block per batch, forward+backward split ----------
// smem: exp(logits) tile. Warp 0: alpha forward [0..m]. Warp 1: beta
// backward [len-1..m]. Warp 2: gold-path numerator.
// den = log(dot(vf,vb)) + Sf + Sb.
__global__ void __launch_bounds__(128, 1)
crf_kernel(const float* __restrict__ logits, const int* __restrict__ labels,
           const void* __restrict__ maskraw, const float* __restrict__ startT,
           const float* __restrict__ endT, const float* __restrict__ trans,
           float* __restrict__ loss0) {
    extern __shared__ float em[];                       // exp(logits), len*LL used
    __shared__ __align__(16) ull pdf[2][32], pdb[2][32];
    __shared__ float vf[64], vb[64];
    __shared__ float Ssh[2];
    __shared__ float res_den, res_num;

    int b = blockIdx.x;
    int tid = threadIdx.x;
    int wid = tid >> 5;
    int u = tid & 31;

    const float* lrow0 = logits + (size_t)b * TT * LL;

    // mask encoding + length (contiguous prefix)
    int mw = *(const int*)maskraw;
    int mode = (mw == 1) ? 0 : ((mw == 0x01010101) ? 1 : 2);
    int cnt = 0;
    for (int t = u; t < TT; t += 32) cnt += mask_on(maskraw, mode, b * TT + t) ? 1 : 0;
    int len = wred_addi(cnt);
    int m = len >> 1;

    // pipelined preload of exp(logits): 8 independent coalesced LDGs per iter
    {
        int total = (len * LL + 1023) & ~1023;
        if (total > TT * LL) total = TT * LL;
        for (int base = 0; base < total; base += 1024) {
            float v[8];
#pragma unroll
            for (int k = 0; k < 8; k++) v[k] = lrow0[base + k * 128 + tid];
#pragma unroll
            for (int k = 0; k < 8; k++) em[base + k * 128 + tid] = __expf(v[k]);
        }
    }
    if (tid < 64) { vf[tid] = 0.0f; vb[tid] = 0.0f; }
    __syncthreads();

    int j0 = 2 * u, j1 = 2 * u + 1;
    bool act = (u < 25);
    int jc = act ? j0 : 0;

    if (wid == 0) {
        // ---- forward: alpha over [0..m] ----
        ull EF0[25], EF1[25];
#pragma unroll
        for (int i = 0; i < 25; i++) {
            float a0 = 0.0f, a1 = 0.0f, d0 = 0.0f, d1 = 0.0f;
            if (act) {
                a0 = __expf(trans[(2 * i) * LL + j0]);
                a1 = __expf(trans[(2 * i + 1) * LL + j0]);
                d0 = __expf(trans[(2 * i) * LL + j1]);
                d1 = __expf(trans[(2 * i + 1) * LL + j1]);
            }
            EF0[i] = pack2(a0, a1);
            EF1[i] = pack2(d0, d1);
        }

        float vx = 0.0f, vy = 0.0f;
        if (act) {
            vx = __expf(startT[j0] + lrow0[j0]);
            vy = __expf(startT[j1] + lrow0[j1]);
        }
        float S = 0.0f;
        float wx = em[1 * LL + jc];
        float wy = em[1 * LL + jc + 1];

        for (int t = 1; t <= m; t++) {
            int buf = t & 1;
            pdf[buf][u] = pack2(vx, vy);
            __syncwarp();
            // prefetch next step's em pair (index (m+1)*LL valid: m+1 < len)
            float wnx = em[(t + 1) * LL + jc];
            float wny = em[(t + 1) * LL + jc + 1];
            const ulonglong2* pp2 = reinterpret_cast<const ulonglong2*>(pdf[buf]);
            ull A0 = 0ull, A1 = 0ull, A2 = 0ull, A3 = 0ull;
            ull B0 = 0ull, B1 = 0ull, B2 = 0ull, B3 = 0ull;
            ulonglong2 Pq0 = pp2[0];
            float v0b, dmy;
            unpack2(Pq0.x, v0b, dmy);
            fma2(A0, Pq0.x, EF0[0]);
            fma2(A1, Pq0.y, EF0[1]);
            fma2(B0, Pq0.x, EF1[0]);
            fma2(B1, Pq0.y, EF1[1]);
#pragma unroll
            for (int q = 1; q < 12; q++) {
                ulonglong2 Pq = pp2[q];
                if (q & 1) {
                    fma2(A2, Pq.x, EF0[2 * q]);
                    fma2(A3, Pq.y, EF0[2 * q + 1]);
                    fma2(B2, Pq.x, EF1[2 * q]);
                    fma2(B3, Pq.y, EF1[2 * q + 1]);
                } else {
                    fma2(A0, Pq.x, EF0[2 * q]);
                    fma2(A1, Pq.y, EF0[2 * q + 1]);
                    fma2(B0, Pq.x, EF1[2 * q]);
                    fma2(B1, Pq.y, EF1[2 * q + 1]);
                }
            }
            ull P24 = pdf[buf][24];
            fma2(A2, P24, EF0[24]);
            fma2(B2, P24, EF1[24]);
            float r = frcp_fast(v0b);
            S += __logf(v0b);
            ull sA = add2(add2(A0, A1), add2(A2, A3));
            ull sB = add2(add2(B0, B1), add2(B2, B3));
            float e0, e1, f0, f1;
            unpack2(sA, e0, e1);
            unpack2(sB, f0, f1);
            vx = (e0 + e1) * wx * r;
            vy = (f0 + f1) * wy * r;
            wx = wnx;
            wy = wny;
        }

        if (act) { vf[j0] = vx; vf[j1] = vy; }
        if (u == 0) Ssh[0] = S;
    } else if (wid == 1) {
        // ---- backward: beta over [len-1..m] ----
        ull EB0[25], EB1[25];
#pragma unroll
        for (int k = 0; k < 25; k++) {
            float a0 = 0.0f, a1 = 0.0f, d0 = 0.0f, d1 = 0.0f;
            if (act) {
                a0 = __expf(trans[j0 * LL + 2 * k]);
                a1 = __expf(trans[j0 * LL + 2 * k + 1]);
                d0 = __expf(trans[j1 * LL + 2 * k]);
                d1 = __expf(trans[j1 * LL + 2 * k + 1]);
            }
            EB0[k] = pack2(a0, a1);
            EB1[k] = pack2(d0, d1);
        }

        float ux = 0.0f, uy = 0.0f;
        if (act) {
            ux = __expf(endT[j0]);
            uy = __expf(endT[j1]);
        }
        float S = 0.0f;
        float wx = em[(len - 1) * LL + jc];
        float wy = em[(len - 1) * LL + jc + 1];

        for (int cur = len - 2; cur >= m; cur--) {
            int buf = cur & 1;
            pdb[buf][u] = pack2(ux * wx, uy * wy);  // q = w_{cur+1} ∘ u
            __syncwarp();
            float wnx = em[cur * LL + jc];  // prefetch for next iteration
            float wny = em[cur * LL + jc + 1];
            const ulonglong2* pp2 = reinterpret_cast<const ulonglong2*>(pdb[buf]);
            ull A0 = 0ull, A1 = 0ull, A2 = 0ull, A3 = 0ull;
            ull B0 = 0ull, B1 = 0ull, B2 = 0ull, B3 = 0ull;
            ulonglong2 Pq0 = pp2[0];
            float q0b, dmy;
            unpack2(Pq0.x, q0b, dmy);
            fma2(A0, Pq0.x, EB0[0]);
            fma2(A1, Pq0.y, EB0[1]);
            fma2(B0, Pq0.x, EB1[0]);
            fma2(B1, Pq0.y, EB1[1]);
#pragma unroll
            for (int q = 1; q < 12; q++) {
                ulonglong2 Pq = pp2[q];
                if (q & 1) {
                    fma2(A2, Pq.x, EB0[2 * q]);
                    fma2(A3, Pq.y, EB0[2 * q + 1]);
                    fma2(B2, Pq.x, EB1[2 * q]);
                    fma2(B3, Pq.y, EB1[2 * q + 1]);
                } else {
                    fma2(A0, Pq.x, EB0[2 * q]);
                    fma2(A1, Pq.y, EB0[2 * q + 1]);
                    fma2(B0, Pq.x, EB1[2 * q]);
                    fma2(B1, Pq.y, EB1[2 * q + 1]);
                }
            }
            ull P24 = pdb[buf][24];
            fma2(A2, P24, EB0[24]);
            fma2(B2, P24, EB1[24]);
            float r = frcp_fast(q0b);
            S += __logf(q0b);
            ull sA = add2(add2(A0, A1), add2(A2, A3));
            ull sB = add2(add2(B0, B1), add2(B2, B3));
            float e0, e1, f0, f1;
            unpack2(sA, e0, e1);
            unpack2(sB, f0, f1);
            ux = (e0 + e1) * r;
            uy = (f0 + f1) * r;
            wx = wnx;
            wy = wny;
        }

        if (act) { vb[j0] = ux; vb[j1] = uy; }
        if (u == 0) Ssh[1] = S;
    } else if (wid == 2) {
        // ---- numerator (prefix mask => prev tag = labels[t-1]) ----
        float np = 0.0f;
        const int* lab = labels + b * TT;
        for (int t = u; t < len; t += 32) {
            int tag = lab[t];
            float emv = lrow0[(size_t)t * LL + tag];
            np += (t == 0) ? (startT[tag] + emv)
                           : (trans[lab[t - 1] * LL + tag] + emv);
            if (t == len - 1) np += endT[tag];
        }
        float num = wred_addf(np);
        if (u == 0) res_num = num;
    }
    __syncthreads();

    // combine: den = log(dot(vf,vb)) + Sf + Sb
    if (wid == 0) {
        float s = act ? (vf[j0] * vb[j0] + vf[j1] * vb[j1]) : 0.0f;
        s = wred_addf(s);
        if (u == 0) res_den = __logf(s) + Ssh[0] + Ssh[1];
    }
    __syncthreads();
    if (tid == 0) atomicAdd(loss0, (res_den - res_num) * (1.0f / (float)BB));
}

extern "C" void kernel_launch(void* const* d_in, const int* in_sizes, int n_in,
                              void* d_out, int out_size) {
    (void)in_sizes; (void)n_in; (void)out_size;
    const float* emb    = (const float*)d_in[0];
    const int*   labels = (const int*)d_in[1];
    const void*  mask   = d_in[2];
    const float* W      = (const float*)d_in[3];
    const float* bias   = (const float*)d_in[4];
    const float* startT = (const float*)d_in[5];
    const float* endT   = (const float*)d_in[6];
    const float* trans  = (const float*)d_in[7];

    float* out = (float*)d_out;
    float* logits = out + 1;  // output layout: [ -loss, logits(B*T*L) ]

    const int dyn = TT * LL * sizeof(float);  // 102,400 B
    cudaFuncSetAttribute(crf_kernel, cudaFuncAttributeMaxDynamicSharedMemorySize, dyn);

    gemm_kernel<<<256, 128>>>(emb, W, bias, logits, out);
    crf_kernel<<<BB, 128, dyn>>>(logits, labels, mask, startT, endT, trans, out);
}

// round 10
// speedup vs baseline: 2.2022x; 1.0377x over previous
#include <cuda_runtime.h>
#include <cuda_bf16.h>

#define BB 64
#define TT 512
#define DD 768
#define LL 50

typedef unsigned long long ull;

// ---------- f32x2 helpers (sm_103a packed fp32) ----------
__device__ __forceinline__ ull pack2(float x, float y) {
    ull r;
    asm("mov.b64 %0, {%1,%2};" : "=l"(r) : "f"(x), "f"(y));
    return r;
}
__device__ __forceinline__ void unpack2(ull v, float& x, float& y) {
    asm("mov.b64 {%0,%1}, %2;" : "=f"(x), "=f"(y) : "l"(v));
}
__device__ __forceinline__ void fma2(ull& d, ull a, ull b) {
    asm("fma.rn.f32x2 %0, %1, %2, %0;" : "+l"(d) : "l"(a), "l"(b));
}
__device__ __forceinline__ ull add2(ull a, ull b) {
    ull r;
    asm("add.rn.f32x2 %0, %1, %2;" : "=l"(r) : "l"(a), "l"(b));
    return r;
}
__device__ __forceinline__ float frcp_fast(float x) {
    float r;
    asm("rcp.approx.f32 %0, %1;" : "=f"(r) : "f"(x));
    return r;
}
__device__ __forceinline__ float wred_addf(float x) {
#pragma unroll
    for (int o = 16; o > 0; o >>= 1) x += __shfl_xor_sync(0xffffffffu, x, o);
    return x;
}
__device__ __forceinline__ int wred_addi(int x) {
#pragma unroll
    for (int o = 16; o > 0; o >>= 1) x += __shfl_xor_sync(0xffffffffu, x, o);
    return x;
}

// ---------- GEMM: logits = emb @ W + b  (register double-buffered) ----------
#define AP 129
__global__ void __launch_bounds__(128, 2)
gemm_kernel(const float* __restrict__ A, const float* __restrict__ W,
            const float* __restrict__ bias, float* __restrict__ logits,
            float* __restrict__ loss0) {
    __shared__ float Ash[64 * AP];               // [kk][row] transposed
    __shared__ __align__(16) float Wsh[64 * 52]; // [kk][j] pad 52
    __shared__ float bsh[52];

    int tid = threadIdx.x;
    if (blockIdx.x == 0 && tid == 0) *loss0 = 0.0f;
    if (tid < 52) bsh[tid] = (tid < LL) ? bias[tid] : 0.0f;

    ull acc[26];
#pragma unroll
    for (int p = 0; p < 26; p++) acc[p] = 0ull;

    const float4* Ag = reinterpret_cast<const float4*>(A);
    int rowbase = blockIdx.x * 128;

    // per-thread (r,q) assignment for A tile, fixed across tiles
    // idx = it*128+tid; q = idx&15 (16B chunk), r = idx>>4 (row within tile)
    float4 fa[16];
    float wv[26];

    // prefetch tile 0
#pragma unroll
    for (int it = 0; it < 16; it++) {
        int idx = it * 128 + tid;
        int q = idx & 15;
        int r = idx >> 4;
        fa[it] = Ag[(size_t)(rowbase + r) * (DD / 4) + q];
    }
#pragma unroll
    for (int it = 0; it < 26; it++) {
        int idx = it * 128 + tid;
        int kk = idx / 52;
        int j = idx - kk * 52;
        wv[it] = (j < LL) ? W[(size_t)kk * LL + j] : 0.0f;
    }

    for (int kt = 0; kt < DD / 64; kt++) {
        __syncthreads();  // previous compute done reading smem
        // store staged tile to smem
#pragma unroll
        for (int it = 0; it < 16; it++) {
            int idx = it * 128 + tid;
            int q = idx & 15;
            int r = idx >> 4;
            Ash[(4 * q + 0) * AP + r] = fa[it].x;
            Ash[(4 * q + 1) * AP + r] = fa[it].y;
            Ash[(4 * q + 2) * AP + r] = fa[it].z;
            Ash[(4 * q + 3) * AP + r] = fa[it].w;
        }
#pragma unroll
        for (int it = 0; it < 26; it++) {
            int idx = it * 128 + tid;
            if (idx < 64 * 52) Wsh[idx] = wv[it];
        }
        // issue next tile's loads (latency overlapped with compute below)
        if (kt < DD / 64 - 1) {
#pragma unroll
            for (int it = 0; it < 16; it++) {
                int idx = it * 128 + tid;
                int q = idx & 15;
                int r = idx >> 4;
                fa[it] = Ag[(size_t)(rowbase + r) * (DD / 4) + (kt + 1) * 16 + q];
            }
#pragma unroll
            for (int it = 0; it < 26; it++) {
                int idx = it * 128 + tid;
                int kk = idx / 52;
                int j = idx - kk * 52;
                wv[it] = (j < LL) ? W[(size_t)((kt + 1) * 64 + kk) * LL + j] : 0.0f;
            }
        }
        __syncthreads();  // smem tile ready
#pragma unroll 8
        for (int kk = 0; kk < 64; kk++) {
            float a = Ash[kk * AP + tid];
            ull ap = pack2(a, a);
            const ulonglong2* w2 = reinterpret_cast<const ulonglong2*>(Wsh + kk * 52);
#pragma unroll
            for (int p = 0; p < 13; p++) {
                ulonglong2 w = w2[p];
                fma2(acc[2 * p + 0], ap, w.x);
                fma2(acc[2 * p + 1], ap, w.y);
            }
        }
    }
    __syncthreads();
    float* st = Ash;
#pragma unroll
    for (int p = 0; p < 25; p++) {
        float x, y;
        unpack2(acc[p], x, y);
        st[tid * 50 + 2 * p + 0] = x + bsh[2 * p + 0];
        st[tid * 50 + 2 * p + 1] = y + bsh[2 * p + 1];
    }
    __syncthreads();
    size_t base = (size_t)blockIdx.x * (128 * LL);
    for (int idx = tid; idx < 128 * LL; idx += 128)
        logits[base + idx] = st[idx];
}

// ---------- mask decode ----------
__device__ __forceinline__ bool mask_on(const void* m, int mode, int idx) {
    if (mode == 0) return ((const int*)m)[idx] != 0;
    if (mode == 1) return ((const unsigned char*)m)[idx] != 0;
    return ((const float*)m)[idx] != 0.0f;
}

// ---------- CRF: one block per batch, forward+backward split ----------
__global__ void __launch_bounds__(128, 1)
crf_kernel(const float* __restrict__ logits, const int* __restrict__ labels,
           const void* __restrict__ maskraw, const float* __restrict__ startT,
           const float* __restrict__ endT, const float* __restrict__ trans,
           float* __restrict__ loss0) {
    extern __shared__ float em[];                       // exp(logits), len*LL used
    __shared__ __align__(16) ull pdf[2][32], pdb[2][32];
    __shared__ float vf[64], vb[64];
    __shared__ float Ssh[2];
    __shared__ float res_den, res_num;

    int b = blockIdx.x;
    int tid = threadIdx.x;
    int wid = tid >> 5;
    int u = tid & 31;

    const float* lrow0 = logits + (size_t)b * TT * LL;

    int mw = *(const int*)maskraw;
    int mode = (mw == 1) ? 0 : ((mw == 0x01010101) ? 1 : 2);
    int cnt = 0;
    for (int t = u; t < TT; t += 32) cnt += mask_on(maskraw, mode, b * TT + t) ? 1 : 0;
    int len = wred_addi(cnt);
    int m = len >> 1;

    // pipelined preload of exp(logits): 8 independent coalesced LDGs per iter
    {
        int total = (len * LL + 1023) & ~1023;
        if (total > TT * LL) total = TT * LL;
        for (int base = 0; base < total; base += 1024) {
            float v[8];
#pragma unroll
            for (int k = 0; k < 8; k++) v[k] = lrow0[base + k * 128 + tid];
#pragma unroll
            for (int k = 0; k < 8; k++) em[base + k * 128 + tid] = __expf(v[k]);
        }
    }
    if (tid < 64) { vf[tid] = 0.0f; vb[tid] = 0.0f; }
    __syncthreads();

    int j0 = 2 * u, j1 = 2 * u + 1;
    bool act = (u < 25);
    int jc = act ? j0 : 0;

    if (wid == 0) {
        // ---- forward: alpha over [0..m] ----
        ull EF0[25], EF1[25];
#pragma unroll
        for (int i = 0; i < 25; i++) {
            float a0 = 0.0f, a1 = 0.0f, d0 = 0.0f, d1 = 0.0f;
            if (act) {
                a0 = __expf(trans[(2 * i) * LL + j0]);
                a1 = __expf(trans[(2 * i + 1) * LL + j0]);
                d0 = __expf(trans[(2 * i) * LL + j1]);
                d1 = __expf(trans[(2 * i + 1) * LL + j1]);
            }
            EF0[i] = pack2(a0, a1);
            EF1[i] = pack2(d0, d1);
        }

        float vx = 0.0f, vy = 0.0f;
        if (act) {
            vx = __expf(startT[j0] + lrow0[j0]);
            vy = __expf(startT[j1] + lrow0[j1]);
        }
        float S = 0.0f;
        float wx = em[1 * LL + jc];
        float wy = em[1 * LL + jc + 1];

        for (int t = 1; t <= m; t++) {
            int buf = t & 1;
            pdf[buf][u] = pack2(vx, vy);
            __syncwarp();
            float wnx = em[(t + 1) * LL + jc];
            float wny = em[(t + 1) * LL + jc + 1];
            const ulonglong2* pp2 = reinterpret_cast<const ulonglong2*>(pdf[buf]);
            ull A0 = 0ull, A1 = 0ull, A2 = 0ull, A3 = 0ull;
            ull B0 = 0ull, B1 = 0ull, B2 = 0ull, B3 = 0ull;
            ulonglong2 Pq0 = pp2[0];
            float v0b, dmy;
            unpack2(Pq0.x, v0b, dmy);
            fma2(A0, Pq0.x, EF0[0]);
            fma2(A1, Pq0.y, EF0[1]);
            fma2(B0, Pq0.x, EF1[0]);
            fma2(B1, Pq0.y, EF1[1]);
#pragma unroll
            for (int q = 1; q < 12; q++) {
                ulonglong2 Pq = pp2[q];
                if (q & 1) {
                    fma2(A2, Pq.x, EF0[2 * q]);
                    fma2(A3, Pq.y, EF0[2 * q + 1]);
                    fma2(B2, Pq.x, EF1[2 * q]);
                    fma2(B3, Pq.y, EF1[2 * q + 1]);
                } else {
                    fma2(A0, Pq.x, EF0[2 * q]);
                    fma2(A1, Pq.y, EF0[2 * q + 1]);
                    fma2(B0, Pq.x, EF1[2 * q]);
                    fma2(B1, Pq.y, EF1[2 * q + 1]);
                }
            }
            ull P24 = pdf[buf][24];
            fma2(A2, P24, EF0[24]);
            fma2(B2, P24, EF1[24]);
            float r = frcp_fast(v0b);
            S += __logf(v0b);
            ull sA = add2(add2(A0, A1), add2(A2, A3));
            ull sB = add2(add2(B0, B1), add2(B2, B3));
            float e0, e1, f0, f1;
            unpack2(sA, e0, e1);
            unpack2(sB, f0, f1);
            vx = (e0 + e1) * wx * r;
            vy = (f0 + f1) * wy * r;
            wx = wnx;
            wy = wny;
        }

        if (act) { vf[j0] = vx; vf[j1] = vy; }
        if (u == 0) Ssh[0] = S;
    } else if (wid == 1) {
        // ---- backward: beta over [len-1..m] ----
        ull EB0[25], EB1[25];
#pragma unroll
        for (int k = 0; k < 25; k++) {
            float a0 = 0.0f, a1 = 0.0f, d0 = 0.0f, d1 = 0.0f;
            if (act) {
                a0 = __expf(trans[j0 * LL + 2 * k]);
                a1 = __expf(trans[j0 * LL + 2 * k + 1]);
                d0 = __expf(trans[j1 * LL + 2 * k]);
                d1 = __expf(trans[j1 * LL + 2 * k + 1]);
            }
            EB0[k] = pack2(a0, a1);
            EB1[k] = pack2(d0, d1);
        }

        float ux = 0.0f, uy = 0.0f;
        if (act) {
            ux = __expf(endT[j0]);
            uy = __expf(endT[j1]);
        }
        float S = 0.0f;
        float wx = em[(len - 1) * LL + jc];
        float wy = em[(len - 1) * LL + jc + 1];

        for (int cur = len - 2; cur >= m; cur--) {
            int buf = cur & 1;
            pdb[buf][u] = pack2(ux * wx, uy * wy);
            __syncwarp();
            float wnx = em[cur * LL + jc];
            float wny = em[cur * LL + jc + 1];
            const ulonglong2* pp2 = reinterpret_cast<const ulonglong2*>(pdb[buf]);
            ull A0 = 0ull, A1 = 0ull, A2 = 0ull, A3 = 0ull;
            ull B0 = 0ull, B1 = 0ull, B2 = 0ull, B3 = 0ull;
            ulonglong2 Pq0 = pp2[0];
            float q0b, dmy;
            unpack2(Pq0.x, q0b, dmy);
            fma2(A0, Pq0.x, EB0[0]);
            fma2(A1, Pq0.y, EB0[1]);
            fma2(B0, Pq0.x, EB1[0]);
            fma2(B1, Pq0.y, EB1[1]);
#pragma unroll
            for (int q = 1; q < 12; q++) {
                ulonglong2 Pq = pp2[q];
                if (q & 1) {
                    fma2(A2, Pq.x, EB0[2 * q]);
                    fma2(A3, Pq.y, EB0[2 * q + 1]);
                    fma2(B2, Pq.x, EB1[2 * q]);
                    fma2(B3, Pq.y, EB1[2 * q + 1]);
                } else {
                    fma2(A0, Pq.x, EB0[2 * q]);
                    fma2(A1, Pq.y, EB0[2 * q + 1]);
                    fma2(B0, Pq.x, EB1[2 * q]);
                    fma2(B1, Pq.y, EB1[2 * q + 1]);
                }
            }
            ull P24 = pdb[buf][24];
            fma2(A2, P24, EB0[24]);
            fma2(B2, P24, EB1[24]);
            float r = frcp_fast(q0b);
            S += __logf(q0b);
            ull sA = add2(add2(A0, A1), add2(A2, A3));
            ull sB = add2(add2(B0, B1), add2(B2, B3));
            float e0, e1, f0, f1;
            unpack2(sA, e0, e1);
            unpack2(sB, f0, f1);
            ux = (e0 + e1) * r;
            uy = (f0 + f1) * r;
            wx = wnx;
            wy = wny;
        }

        if (act) { vb[j0] = ux; vb[j1] = uy; }
        if (u == 0) Ssh[1] = S;
    } else if (wid == 2) {
        // ---- numerator ----
        float np = 0.0f;
        const int* lab = labels + b * TT;
        for (int t = u; t < len; t += 32) {
            int tag = lab[t];
            float emv = lrow0[(size_t)t * LL + tag];
            np += (t == 0) ? (startT[tag] + emv)
                           : (trans[lab[t - 1] * LL + tag] + emv);
            if (t == len - 1) np += endT[tag];
        }
        float num = wred_addf(np);
        if (u == 0) res_num = num;
    }
    __syncthreads();

    if (wid == 0) {
        float s = act ? (vf[j0] * vb[j0] + vf[j1] * vb[j1]) : 0.0f;
        s = wred_addf(s);
        if (u == 0) res_den = __logf(s) + Ssh[0] + Ssh[1];
    }
    __syncthreads();
    if (tid == 0) atomicAdd(loss0, (res_den - res_num) * (1.0f / (float)BB));
}

extern "C" void kernel_launch(void* const* d_in, const int* in_sizes, int n_in,
                              void* d_out, int out_size) {
    (void)in_sizes; (void)n_in; (void)out_size;
    const float* emb    = (const float*)d_in[0];
    const int*   labels = (const int*)d_in[1];
    const void*  mask   = d_in[2];
    const float* W      = (const float*)d_in[3];
    const float* bias   = (const float*)d_in[4];
    const float* startT = (const float*)d_in[5];
    const float* endT   = (const float*)d_in[6];
    const float* trans  = (const float*)d_in[7];

    float* out = (float*)d_out;
    float* logits = out + 1;  // output layout: [ -loss, logits(B*T*L) ]

    const int dyn = TT * LL * sizeof(float);  // 102,400 B
    cudaFuncSetAttribute(crf_kernel, cudaFuncAttributeMaxDynamicSharedMemorySize, dyn);

    gemm_kernel<<<256, 128>>>(emb, W, bias, logits, out);
    crf_kernel<<<BB, 128, dyn>>>(logits, labels, mask, startT, endT, trans, out);
}